// round 1
// baseline (speedup 1.0000x reference)
#include <cuda_runtime.h>
#include <math.h>

#define BATCH 2
#define CIN   512
#define NTOK  4096
#define EMB   512
#define NH    8
#define HD    64
#define QT    64
#define KT    64
#define NQT   (NTOK/QT)   // 64

// Scratch: Q/K/V in [b][head][n][d] layout, 16 MB each.
__device__ float g_Q[BATCH*NH*NTOK*HD];
__device__ float g_K[BATCH*NH*NTOK*HD];
__device__ float g_V[BATCH*NH*NTOK*HD];

// ---------------------------------------------------------------------------
// Projection: O[b][h][n][d] = X_tok[b][n][:] @ W[e][:] + bias[e],  e = h*64+d
// X_tok[b][n][c] = X[b*C*N + c*N + n]  (channel-strided gather, n contiguous)
// Classic 128x128 tile SGEMM, BK=8, 256 threads, 8x8 micro-tile.
// ---------------------------------------------------------------------------
__global__ __launch_bounds__(256) void proj_kernel(
    const float* __restrict__ query, const float* __restrict__ key,
    const float* __restrict__ Wq, const float* __restrict__ bq,
    const float* __restrict__ Wk, const float* __restrict__ bk,
    const float* __restrict__ Wv, const float* __restrict__ bv)
{
    const int z = blockIdx.z;
    const float* X    = (z == 0) ? query : key;
    const float* W    = (z == 0) ? Wq : (z == 1 ? Wk : Wv);
    const float* bias = (z == 0) ? bq : (z == 1 ? bk : bv);
    float* O          = (z == 0) ? g_Q : (z == 1 ? g_K : g_V);

    const int b  = blockIdx.x >> 5;          // 32 n-tiles of 128 per batch
    const int n0 = (blockIdx.x & 31) * 128;
    const int e0 = blockIdx.y * 128;

    __shared__ float As[8][128];
    __shared__ float Ws[8][128];

    const int tid = threadIdx.x;
    const int tx  = tid & 15;
    const int ty  = tid >> 4;

    float acc[8][8];
    #pragma unroll
    for (int i = 0; i < 8; i++)
        #pragma unroll
        for (int j = 0; j < 8; j++) acc[i][j] = 0.f;

    const size_t xbase = (size_t)b * CIN * NTOK;

    for (int c0 = 0; c0 < CIN; c0 += 8) {
        __syncthreads();
        // A tile: 8 channels x 128 tokens (coalesced: n contiguous)
        #pragma unroll
        for (int i = tid; i < 8 * 128; i += 256) {
            int k = i >> 7, n = i & 127;
            As[k][n] = X[xbase + (size_t)(c0 + k) * NTOK + n0 + n];
        }
        // W tile: one float4 per thread, scatter-store transposed
        {
            int e  = tid >> 1;
            int kq = (tid & 1) * 4;
            const float4 w4 = *(const float4*)&W[(size_t)(e0 + e) * CIN + c0 + kq];
            Ws[kq + 0][e] = w4.x; Ws[kq + 1][e] = w4.y;
            Ws[kq + 2][e] = w4.z; Ws[kq + 3][e] = w4.w;
        }
        __syncthreads();

        #pragma unroll
        for (int k = 0; k < 8; k++) {
            float a[8], w[8];
            *(float4*)&a[0] = *(const float4*)&As[k][ty * 8];
            *(float4*)&a[4] = *(const float4*)&As[k][ty * 8 + 4];
            *(float4*)&w[0] = *(const float4*)&Ws[k][tx * 8];
            *(float4*)&w[4] = *(const float4*)&Ws[k][tx * 8 + 4];
            #pragma unroll
            for (int i = 0; i < 8; i++)
                #pragma unroll
                for (int j = 0; j < 8; j++)
                    acc[i][j] += a[i] * w[j];
        }
    }

    // Epilogue: +bias, write in [b][h][n][d] layout
    #pragma unroll
    for (int i = 0; i < 8; i++) {
        const int n = n0 + ty * 8 + i;
        #pragma unroll
        for (int j = 0; j < 8; j++) {
            const int e = e0 + tx * 8 + j;
            const int h = e >> 6, d = e & 63;
            O[((size_t)(b * NH + h) * NTOK + n) * HD + d] = acc[i][j] + bias[e];
        }
    }
}

// ---------------------------------------------------------------------------
// Flash attention, fp32. One block = 64 queries of one (b, head).
// 64x64 key tiles, causal tile skip. 256 threads, 4x4 micro-tiles.
// Shared (dynamic, 65-float padded rows): Qs, Ks, Vs, Ps = 66,560 B.
// ---------------------------------------------------------------------------
__global__ __launch_bounds__(256) void attn_kernel(float* __restrict__ out)
{
    const int qt = (NQT - 1) - blockIdx.x;   // big blocks first (tail balance)
    const int h  = blockIdx.y;
    const int b  = blockIdx.z;

    extern __shared__ float sm[];
    float* Qs = sm;                 // [64][65]
    float* Ks = Qs + 64 * 65;
    float* Vs = Ks + 64 * 65;
    float* Ps = Vs + 64 * 65;

    const int tid = threadIdx.x;
    const int tx  = tid & 15;
    const int ty  = tid >> 4;

    const size_t base = (size_t)(b * NH + h) * NTOK * HD;

    // Load Q tile, pre-scaled by 1/sqrt(hd) = 0.125
    for (int i = tid; i < QT * HD; i += 256) {
        int qi = i >> 6, d = i & 63;
        Qs[qi * 65 + d] = g_Q[base + (size_t)(qt * QT + qi) * HD + d] * 0.125f;
    }

    float acc[4][4];
    float m_i[4], l_i[4];
    #pragma unroll
    for (int r = 0; r < 4; r++) {
        m_i[r] = -1e30f; l_i[r] = 0.f;
        #pragma unroll
        for (int c = 0; c < 4; c++) acc[r][c] = 0.f;
    }

    for (int j = 0; j <= qt; j++) {
        __syncthreads();
        for (int i = tid; i < KT * HD; i += 256) {
            int kj = i >> 6, d = i & 63;
            size_t g = base + (size_t)(j * KT + kj) * HD + d;
            Ks[kj * 65 + d] = g_K[g];
            Vs[kj * 65 + d] = g_V[g];
        }
        __syncthreads();

        // S = Q K^T (64x64), thread owns rows ty*4..+3, cols tx*4..+3
        float s[4][4];
        #pragma unroll
        for (int r = 0; r < 4; r++)
            #pragma unroll
            for (int c = 0; c < 4; c++) s[r][c] = 0.f;

        #pragma unroll 8
        for (int d = 0; d < HD; d++) {
            float qv[4], kv[4];
            #pragma unroll
            for (int r = 0; r < 4; r++) qv[r] = Qs[(ty * 4 + r) * 65 + d];
            #pragma unroll
            for (int c = 0; c < 4; c++) kv[c] = Ks[(tx * 4 + c) * 65 + d];
            #pragma unroll
            for (int r = 0; r < 4; r++)
                #pragma unroll
                for (int c = 0; c < 4; c++) s[r][c] += qv[r] * kv[c];
        }

        if (j == qt) {   // diagonal tile: mask kj > qi
            #pragma unroll
            for (int r = 0; r < 4; r++)
                #pragma unroll
                for (int c = 0; c < 4; c++)
                    if (tx * 4 + c > ty * 4 + r) s[r][c] = -1e30f;
        }

        // Online softmax per row; row reduce across the 16 tx lanes
        #pragma unroll
        for (int r = 0; r < 4; r++) {
            float mx = fmaxf(fmaxf(s[r][0], s[r][1]), fmaxf(s[r][2], s[r][3]));
            #pragma unroll
            for (int o = 8; o > 0; o >>= 1)
                mx = fmaxf(mx, __shfl_xor_sync(0xffffffffu, mx, o));
            float mnew = fmaxf(m_i[r], mx);
            float p[4], ps = 0.f;
            #pragma unroll
            for (int c = 0; c < 4; c++) { p[c] = __expf(s[r][c] - mnew); ps += p[c]; }
            #pragma unroll
            for (int o = 8; o > 0; o >>= 1)
                ps += __shfl_xor_sync(0xffffffffu, ps, o);
            float scale = __expf(m_i[r] - mnew);
            l_i[r] = l_i[r] * scale + ps;
            m_i[r] = mnew;
            #pragma unroll
            for (int c = 0; c < 4; c++) acc[r][c] *= scale;
            #pragma unroll
            for (int c = 0; c < 4; c++) Ps[(ty * 4 + r) * 65 + tx * 4 + c] = p[c];
        }
        __syncthreads();

        // O += P V  (thread owns rows ty*4..+3, d-cols tx*4..+3)
        #pragma unroll 8
        for (int kj = 0; kj < KT; kj++) {
            float pv[4], vv[4];
            #pragma unroll
            for (int r = 0; r < 4; r++) pv[r] = Ps[(ty * 4 + r) * 65 + kj];
            #pragma unroll
            for (int c = 0; c < 4; c++) vv[c] = Vs[kj * 65 + tx * 4 + c];
            #pragma unroll
            for (int r = 0; r < 4; r++)
                #pragma unroll
                for (int c = 0; c < 4; c++) acc[r][c] += pv[r] * vv[c];
        }
    }

    // Finalize: stage O/l into Ps, then coalesced transposed write-out.
    __syncthreads();
    #pragma unroll
    for (int r = 0; r < 4; r++) {
        float inv = 1.f / l_i[r];
        #pragma unroll
        for (int c = 0; c < 4; c++)
            Ps[(ty * 4 + r) * 65 + tx * 4 + c] = acc[r][c] * inv;
    }
    __syncthreads();
    // out[b][e][n] with e = h*64+d, n = qt*64+qi ; consecutive tid -> consecutive n
    for (int i = tid; i < QT * HD; i += 256) {
        int d = i >> 6, qi = i & 63;
        out[((size_t)(b * EMB + h * HD + d)) * NTOK + qt * QT + qi] = Ps[qi * 65 + d];
    }
}

// ---------------------------------------------------------------------------
extern "C" void kernel_launch(void* const* d_in, const int* in_sizes, int n_in,
                              void* d_out, int out_size)
{
    const float* query = (const float*)d_in[0];
    const float* key   = (const float*)d_in[1];
    const float* Wq    = (const float*)d_in[2];
    const float* bq    = (const float*)d_in[3];
    const float* Wk    = (const float*)d_in[4];
    const float* bk    = (const float*)d_in[5];
    const float* Wv    = (const float*)d_in[6];
    const float* bv    = (const float*)d_in[7];
    float* out = (float*)d_out;

    dim3 pgrid(64, 4, 3);            // (n-tiles*batch, e-tiles, {q,k,v})
    proj_kernel<<<pgrid, 256>>>(query, key, Wq, bq, Wk, bk, Wv, bv);

    const int attn_smem = 4 * 64 * 65 * (int)sizeof(float);   // 66,560 B
    cudaFuncSetAttribute(attn_kernel,
                         cudaFuncAttributeMaxDynamicSharedMemorySize, attn_smem);
    dim3 agrid(NQT, NH, BATCH);
    attn_kernel<<<agrid, 256, attn_smem>>>(out);
}

// round 5
// speedup vs baseline: 3.4432x; 3.4432x over previous
#include <cuda_runtime.h>
#include <stdint.h>

#define NH   8
#define HD   64
#define NTOK 4096
#define EMB  512
#define CIN  512

// Scratch Q/K/V in [b][h][n][d] layout
__device__ float g_Q[2*NH*NTOK*HD];
__device__ float g_K[2*NH*NTOK*HD];
__device__ float g_V[2*NH*NTOK*HD];

__device__ __forceinline__ uint32_t f2tf(float x){
    uint32_t u; asm("cvt.rna.tf32.f32 %0, %1;" : "=r"(u) : "f"(x)); return u;
}
__device__ __forceinline__ float ex2f(float x){
    float r; asm("ex2.approx.ftz.f32 %0, %1;" : "=f"(r) : "f"(x)); return r;
}
// D += A(16x8,tf32,row) * B(8x8,tf32,col)
__device__ __forceinline__ void mma8(float* c, const uint32_t* a, uint32_t b0, uint32_t b1){
    asm volatile("mma.sync.aligned.m16n8k8.row.col.f32.tf32.tf32.f32 "
        "{%0,%1,%2,%3},{%4,%5,%6,%7},{%8,%9},{%0,%1,%2,%3};"
        : "+f"(c[0]),"+f"(c[1]),"+f"(c[2]),"+f"(c[3])
        : "r"(a[0]),"r"(a[1]),"r"(a[2]),"r"(a[3]),"r"(b0),"r"(b1));
}

// ---------------------------------------------------------------------------
// Projection (tf32 mma): O[b][h][n][d] = X_tok @ W^T + bias
// 128x128 tile, BK=16, 256 threads = 8 warps (4x2 warp grid).
// ---------------------------------------------------------------------------
__global__ __launch_bounds__(256, 2) void proj_mma(
    const float* __restrict__ query, const float* __restrict__ key,
    const float* __restrict__ Wq, const float* __restrict__ bq,
    const float* __restrict__ Wk, const float* __restrict__ bk,
    const float* __restrict__ Wv, const float* __restrict__ bv)
{
    const int z = blockIdx.z;
    const float* X    = (z == 0) ? query : key;
    const float* W    = (z == 0) ? Wq : (z == 1 ? Wk : Wv);
    const float* bias = (z == 0) ? bq : (z == 1 ? bk : bv);
    float* O          = (z == 0) ? g_Q : (z == 1 ? g_K : g_V);

    const int b  = blockIdx.x >> 5;
    const int n0 = (blockIdx.x & 31) * 128;
    const int e0 = blockIdx.y * 128;

    __shared__ uint32_t Au[16*132];   // [k][m] k-major
    __shared__ uint32_t Wu[16*132];   // [k][e] k-major

    const int tid = threadIdx.x, lane = tid & 31, w = tid >> 5;
    const int g = lane >> 2, t = lane & 3;
    const int wm = w >> 1, wn = w & 1;

    float acc[2][8][4];
    #pragma unroll
    for (int mb = 0; mb < 2; mb++)
        #pragma unroll
        for (int nb = 0; nb < 8; nb++)
            #pragma unroll
            for (int c = 0; c < 4; c++) acc[mb][nb][c] = 0.f;

    const size_t xbase = (size_t)b * CIN * NTOK;

    for (int c0 = 0; c0 < CIN; c0 += 16) {
        __syncthreads();
        // X tile: 16 c x 128 n (coalesced over n)
        #pragma unroll
        for (int it = 0; it < 2; it++) {
            int i = tid + it*256;
            int c = i >> 5, nq = (i & 31) * 4;
            float4 v = *(const float4*)&X[xbase + (size_t)(c0 + c) * NTOK + n0 + nq];
            uint4 u = { f2tf(v.x), f2tf(v.y), f2tf(v.z), f2tf(v.w) };
            *(uint4*)&Au[c*132 + nq] = u;
        }
        // W tile: 128 e x 16 c, transposed into [c][e]
        #pragma unroll
        for (int it = 0; it < 2; it++) {
            int i = tid + it*256;
            int e = i >> 2, cq = (i & 3) * 4;
            float4 v = *(const float4*)&W[(size_t)(e0 + e) * CIN + c0 + cq];
            Wu[(cq+0)*132 + e] = f2tf(v.x);
            Wu[(cq+1)*132 + e] = f2tf(v.y);
            Wu[(cq+2)*132 + e] = f2tf(v.z);
            Wu[(cq+3)*132 + e] = f2tf(v.w);
        }
        __syncthreads();

        #pragma unroll
        for (int kc = 0; kc < 2; kc++) {
            uint32_t a[2][4];
            #pragma unroll
            for (int mb = 0; mb < 2; mb++) {
                int r = wm*32 + mb*16;
                a[mb][0] = Au[(kc*8+t  )*132 + r + g];
                a[mb][1] = Au[(kc*8+t  )*132 + r + g + 8];
                a[mb][2] = Au[(kc*8+t+4)*132 + r + g];
                a[mb][3] = Au[(kc*8+t+4)*132 + r + g + 8];
            }
            #pragma unroll
            for (int nb = 0; nb < 8; nb++) {
                int e = wn*64 + nb*8;
                uint32_t b0 = Wu[(kc*8+t  )*132 + e + g];
                uint32_t b1 = Wu[(kc*8+t+4)*132 + e + g];
                mma8(acc[0][nb], a[0], b0, b1);
                mma8(acc[1][nb], a[1], b0, b1);
            }
        }
    }

    // Epilogue: +bias, store [b][h][n][d]
    #pragma unroll
    for (int mb = 0; mb < 2; mb++) {
        #pragma unroll
        for (int nb = 0; nb < 8; nb++) {
            int e = e0 + wn*64 + nb*8 + 2*t;
            float2 bb = *(const float2*)&bias[e];
            int h = e >> 6, d = e & 63;
            int n = n0 + wm*32 + mb*16 + g;
            float* o0 = &O[(((size_t)b*NH + h)*NTOK + n)*HD + d];
            float2 v0 = { acc[mb][nb][0] + bb.x, acc[mb][nb][1] + bb.y };
            *(float2*)o0 = v0;
            float2 v1 = { acc[mb][nb][2] + bb.x, acc[mb][nb][3] + bb.y };
            *(float2*)(o0 + 8*HD) = v1;
        }
    }
}

// ---------------------------------------------------------------------------
// Flash attention (tf32 mma). 128-query tile / block, 8 warps x 16 rows.
// Q fragments live in registers for the whole block. KT=64.
// smem strides chosen for conflict-free fragment reads.
// ---------------------------------------------------------------------------
#define KSTR 76
#define VSTR 72
#define PSTR 68
#define OSTR 132

__global__ __launch_bounds__(256, 2) void attn_mma(float* __restrict__ out)
{
    const int qt = 31 - (int)blockIdx.x;     // big tiles first
    const int h  = blockIdx.y;
    const int b  = blockIdx.z;

    extern __shared__ uint32_t smu[];
    uint32_t* Ku = smu;                // [kj][KSTR]  (64 rows)
    uint32_t* Vu = Ku + 64*KSTR;       // [kj][VSTR]
    uint32_t* Pu = Vu + 64*VSTR;       // [r][PSTR]   (128 rows)  also Q stage / O stage
    float*    Osm = (float*)Pu;        // [d][OSTR]

    const int tid = threadIdx.x, lane = tid & 31, w = tid >> 5;
    const int g = lane >> 2, t = lane & 3;
    const int r0 = w*16 + g;

    const size_t base = ((size_t)(b*NH + h)) * NTOK * HD;
    const int qbase = qt * 128;

    // Stage Q (pre-scaled by 1/8 * log2(e)) into Pu, then lift to registers
    const float qsc = 0.125f * 1.4426950408889634f;
    for (int i = tid; i < 128*16; i += 256) {
        int r = i >> 4, d0 = (i & 15) * 4;
        float4 v = *(const float4*)&g_Q[base + (size_t)(qbase + r)*HD + d0];
        uint4 u = { f2tf(v.x*qsc), f2tf(v.y*qsc), f2tf(v.z*qsc), f2tf(v.w*qsc) };
        *(uint4*)&Pu[r*PSTR + d0] = u;
    }
    __syncthreads();
    uint32_t qf[8][4];
    #pragma unroll
    for (int kc = 0; kc < 8; kc++) {
        qf[kc][0] = Pu[ r0   *PSTR + kc*8 + t];
        qf[kc][1] = Pu[(r0+8)*PSTR + kc*8 + t];
        qf[kc][2] = Pu[ r0   *PSTR + kc*8 + t + 4];
        qf[kc][3] = Pu[(r0+8)*PSTR + kc*8 + t + 4];
    }

    float acc[8][4];
    #pragma unroll
    for (int nb = 0; nb < 8; nb++)
        #pragma unroll
        for (int c = 0; c < 4; c++) acc[nb][c] = 0.f;
    float m0 = -1e30f, m1 = -1e30f, l0 = 0.f, l1 = 0.f;

    const int ntiles = 2*qt + 2;
    for (int j = 0; j < ntiles; j++) {
        const int n0 = j * 64;
        __syncthreads();
        // load K,V tile (64 keys x 64 d) as tf32
        #pragma unroll
        for (int it = 0; it < 4; it++) {
            int i = tid + it*256;
            int kj = i >> 4, d0 = (i & 15) * 4;
            float4 kv = *(const float4*)&g_K[base + (size_t)(n0+kj)*HD + d0];
            uint4 ku = { f2tf(kv.x), f2tf(kv.y), f2tf(kv.z), f2tf(kv.w) };
            *(uint4*)&Ku[kj*KSTR + d0] = ku;
            float4 vv = *(const float4*)&g_V[base + (size_t)(n0+kj)*HD + d0];
            uint4 vu = { f2tf(vv.x), f2tf(vv.y), f2tf(vv.z), f2tf(vv.w) };
            *(uint4*)&Vu[kj*VSTR + d0] = vu;
        }
        __syncthreads();

        // S = Q K^T  (16 rows x 64 keys per warp)
        float s[8][4];
        #pragma unroll
        for (int nb = 0; nb < 8; nb++)
            #pragma unroll
            for (int c = 0; c < 4; c++) s[nb][c] = 0.f;
        #pragma unroll
        for (int kc = 0; kc < 8; kc++)
            #pragma unroll
            for (int nb = 0; nb < 8; nb++) {
                uint32_t b0 = Ku[(nb*8+g)*KSTR + kc*8 + t];
                uint32_t b1 = Ku[(nb*8+g)*KSTR + kc*8 + t + 4];
                mma8(s[nb], qf[kc], b0, b1);
            }

        if (j >= 2*qt) {   // diagonal tiles: causal mask
            const int row = qbase + r0;
            #pragma unroll
            for (int nb = 0; nb < 8; nb++) {
                int col = n0 + nb*8 + 2*t;
                if (col     > row  ) s[nb][0] = -1e30f;
                if (col + 1 > row  ) s[nb][1] = -1e30f;
                if (col     > row+8) s[nb][2] = -1e30f;
                if (col + 1 > row+8) s[nb][3] = -1e30f;
            }
        }

        // online softmax (rows r0 and r0+8), base-2 domain
        float mx0 = -1e30f, mx1 = -1e30f;
        #pragma unroll
        for (int nb = 0; nb < 8; nb++) {
            mx0 = fmaxf(mx0, fmaxf(s[nb][0], s[nb][1]));
            mx1 = fmaxf(mx1, fmaxf(s[nb][2], s[nb][3]));
        }
        mx0 = fmaxf(mx0, __shfl_xor_sync(0xffffffffu, mx0, 1));
        mx0 = fmaxf(mx0, __shfl_xor_sync(0xffffffffu, mx0, 2));
        mx1 = fmaxf(mx1, __shfl_xor_sync(0xffffffffu, mx1, 1));
        mx1 = fmaxf(mx1, __shfl_xor_sync(0xffffffffu, mx1, 2));
        float mn0 = fmaxf(m0, mx0), mn1 = fmaxf(m1, mx1);
        float sc0 = ex2f(m0 - mn0), sc1 = ex2f(m1 - mn1);
        float ps0 = 0.f, ps1 = 0.f;
        uint32_t* pr0 = &Pu[ r0   *PSTR + 2*t];
        uint32_t* pr1 = &Pu[(r0+8)*PSTR + 2*t];
        #pragma unroll
        for (int nb = 0; nb < 8; nb++) {
            float p0 = ex2f(s[nb][0]-mn0), p1 = ex2f(s[nb][1]-mn0);
            float p2 = ex2f(s[nb][2]-mn1), p3 = ex2f(s[nb][3]-mn1);
            ps0 += p0 + p1;  ps1 += p2 + p3;
            acc[nb][0] *= sc0; acc[nb][1] *= sc0;
            acc[nb][2] *= sc1; acc[nb][3] *= sc1;
            pr0[nb*8+0] = f2tf(p0); pr0[nb*8+1] = f2tf(p1);
            pr1[nb*8+0] = f2tf(p2); pr1[nb*8+1] = f2tf(p3);
        }
        ps0 += __shfl_xor_sync(0xffffffffu, ps0, 1);
        ps0 += __shfl_xor_sync(0xffffffffu, ps0, 2);
        ps1 += __shfl_xor_sync(0xffffffffu, ps1, 1);
        ps1 += __shfl_xor_sync(0xffffffffu, ps1, 2);
        l0 = l0*sc0 + ps0;  l1 = l1*sc1 + ps1;
        m0 = mn0;  m1 = mn1;
        __syncwarp();

        // O += P V
        #pragma unroll
        for (int kc = 0; kc < 8; kc++) {
            uint32_t pa[4];
            pa[0] = Pu[ r0   *PSTR + kc*8 + t];
            pa[1] = Pu[(r0+8)*PSTR + kc*8 + t];
            pa[2] = Pu[ r0   *PSTR + kc*8 + t + 4];
            pa[3] = Pu[(r0+8)*PSTR + kc*8 + t + 4];
            #pragma unroll
            for (int nb = 0; nb < 8; nb++) {
                uint32_t b0 = Vu[(kc*8+t  )*VSTR + nb*8 + g];
                uint32_t b1 = Vu[(kc*8+t+4)*VSTR + nb*8 + g];
                mma8(acc[nb], pa, b0, b1);
            }
        }
    }

    // finalize: /l, stage transposed, coalesced write out[b][e][n]
    float inv0 = 1.f / l0, inv1 = 1.f / l1;
    #pragma unroll
    for (int nb = 0; nb < 8; nb++) {
        acc[nb][0] *= inv0; acc[nb][1] *= inv0;
        acc[nb][2] *= inv1; acc[nb][3] *= inv1;
    }
    __syncthreads();
    #pragma unroll
    for (int nb = 0; nb < 8; nb++) {
        int d = nb*8 + 2*t;
        Osm[(d  )*OSTR + r0    ] = acc[nb][0];
        Osm[(d+1)*OSTR + r0    ] = acc[nb][1];
        Osm[(d  )*OSTR + r0 + 8] = acc[nb][2];
        Osm[(d+1)*OSTR + r0 + 8] = acc[nb][3];
    }
    __syncthreads();
    const size_t obase = ((size_t)b*EMB + h*HD) * NTOK + qbase;
    for (int i = tid; i < 64*128; i += 256) {
        int d = i >> 7, n = i & 127;
        out[obase + (size_t)d * NTOK + n] = Osm[d*OSTR + n];
    }
}

// ---------------------------------------------------------------------------
extern "C" void kernel_launch(void* const* d_in, const int* in_sizes, int n_in,
                              void* d_out, int out_size)
{
    const float* query = (const float*)d_in[0];
    const float* key   = (const float*)d_in[1];
    const float* Wq    = (const float*)d_in[2];
    const float* bq    = (const float*)d_in[3];
    const float* Wk    = (const float*)d_in[4];
    const float* bk    = (const float*)d_in[5];
    const float* Wv    = (const float*)d_in[6];
    const float* bv    = (const float*)d_in[7];
    float* out = (float*)d_out;

    dim3 pgrid(64, 4, 3);
    proj_mma<<<pgrid, 256>>>(query, key, Wq, bq, Wk, bk, Wv, bv);

    const int attn_smem = (64*KSTR + 64*VSTR + 128*PSTR) * (int)sizeof(uint32_t); // 72,704 B
    cudaFuncSetAttribute(attn_mma,
                         cudaFuncAttributeMaxDynamicSharedMemorySize, attn_smem);
    dim3 agrid(32, NH, 2);
    attn_mma<<<agrid, 256, attn_smem>>>(out);
}